// round 17
// baseline (speedup 1.0000x reference)
#include <cuda_runtime.h>
#include <cstdint>

#define HID  64
#define FEAT 9
#define TT   36
#define BLK  256
#define BPB  128   // batch rows per block

// ---- shared layout (float offsets) ----
#define OFF_WG     0         // [64][41 kpair][4 gate][2 parity] = 20992
#define OFF_B2     20992     // [64][4] pairs (bias,0) = 512
#define OFF_WGH    21504     // [64][9] = 576
#define OFF_BGH    22080     // 64
#define OFF_WHIST  22144     // [9][64] = 576
#define OFF_BHIST  22720     // 12
#define OFF_WGXD   22732     // 12
#define OFF_BGX    22744     // 12
#define OFF_WFEAT  22756     // 84
#define OFF_BFEAT  22840     // 12
#define OFF_WCOMB  22852     // 164
#define OFF_BCOMB  23016     // 12
#define OFF_INV    23028     // 36
#define OFF_H      23064     // [128][68]
#define OFF_C      (OFF_H + BPB*68)
#define OFF_XC     (OFF_C + BPB*68)      // [128][13] xc exchange (odd stride)
#define OFF_CCB    (OFF_XC + BPB*13)     // [128][13] c_c exchange
#define SMEM_FLOATS (OFF_CCB + BPB*13)
#define SMEM_BYTES  (SMEM_FLOATS * 4)    // ~175 KB

__device__ float g_denom[TT];
__device__ float g_partials[1024];

typedef unsigned long long u64;

__device__ __forceinline__ void fma2(u64& acc, u64 a, u64 b) {
    asm("fma.rn.f32x2 %0, %1, %2, %0;" : "+l"(acc) : "l"(a), "l"(b));
}
__device__ __forceinline__ u64 pack2(float lo, float hi) {
    u64 r; asm("mov.b64 %0, {%1, %2};" : "=l"(r) : "f"(lo), "f"(hi)); return r;
}
__device__ __forceinline__ float2 unpack2(u64 v) {
    float2 r; asm("mov.b64 {%0, %1}, %2;" : "=f"(r.x), "=f"(r.y) : "l"(v)); return r;
}
__device__ __forceinline__ float fsigmoid(float x) {
    return __fdividef(1.0f, 1.0f + __expf(-x));
}
__device__ __forceinline__ float ftanhx(float x) {
    float e = __expf(2.0f * x);
    return 1.0f - __fdividef(2.0f, e + 1.0f);
}

// ---- denom: zero bins, then coalesced accumulate (exact-integer atomics) ----
__global__ void zero_denom_kernel() {
    if (threadIdx.x < TT) g_denom[threadIdx.x] = 0.0f;
}
__global__ void denom_kernel(const float* __restrict__ masks, int B) {
    __shared__ float bins[TT];
    if (threadIdx.x < TT) bins[threadIdx.x] = 0.0f;
    __syncthreads();
    int idx = blockIdx.x * blockDim.x + threadIdx.x;
    if (idx < B * TT) {
        int t = idx % TT;
        const float* p = masks + (size_t)idx * FEAT;
        float sv = 0.0f;
        #pragma unroll
        for (int f = 0; f < FEAT; f++) sv += p[f];
        atomicAdd(&bins[t], sv);
    }
    __syncthreads();
    if (threadIdx.x < TT) atomicAdd(&g_denom[threadIdx.x], bins[threadIdx.x]);
}

__global__ void __launch_bounds__(BLK)
rits_main_kernel(const float* __restrict__ values,
                 const float* __restrict__ masks,
                 const float* __restrict__ deltas,
                 const float* __restrict__ Wgh, const float* __restrict__ bgh,
                 const float* __restrict__ Wgx, const float* __restrict__ bgx,
                 const float* __restrict__ Whist, const float* __restrict__ bhist,
                 const float* __restrict__ Wfeat, const float* __restrict__ bfeat,
                 const float* __restrict__ Wcomb, const float* __restrict__ bcomb,
                 const float* __restrict__ Wih, const float* __restrict__ Whh,
                 const float* __restrict__ bih, const float* __restrict__ bhh,
                 float* __restrict__ out, int B) {
    extern __shared__ float s[];
    const int tid = threadIdx.x;
    const int row = tid & (BPB - 1);    // batch row within block
    const int role = tid >> 7;          // 0: units 0-31 / even f; 1: units 32-63 / odd f
    const int jbase = role << 5;
    const int qbase = role << 3;
    const int b = blockIdx.x * BPB + row;

    // ---- stage gate weights: [j][kp][gate][parity], k = 2*kp+parity ----
    for (int idx = tid; idx < 64 * 328; idx += BLK) {
        int j = idx / 328, r = idx - j * 328;
        int kp = r >> 3, g = (r & 7) >> 1, p = r & 1;
        int k = 2 * kp + p;
        int rw = g * HID + j;
        s[OFF_WG + idx] = (k < 18) ? Wih[rw * 18 + k] : Whh[rw * HID + (k - 18)];
    }
    if (tid < 256) {
        int j = tid >> 2, g = tid & 3;
        s[OFF_B2 + tid * 2]     = bih[g * HID + j] + bhh[g * HID + j];
        s[OFF_B2 + tid * 2 + 1] = 0.0f;
    }
    for (int idx = tid; idx < 576; idx += BLK) {
        s[OFF_WGH + idx] = Wgh[idx];
        s[OFF_WHIST + idx] = Whist[idx];
    }
    if (tid < 164) s[OFF_WCOMB + tid] = (tid < 162) ? Wcomb[tid] : 0.0f;
    if (tid < 64) s[OFF_BGH + tid] = bgh[tid];
    if (tid < 12) {
        s[OFF_BHIST + tid] = (tid < 9) ? bhist[tid] : 0.0f;
        s[OFF_WGXD + tid]  = (tid < 9) ? Wgx[tid * FEAT + tid] : 0.0f;
        s[OFF_BGX + tid]   = (tid < 9) ? bgx[tid] : 0.0f;
        s[OFF_BFEAT + tid] = (tid < 9) ? bfeat[tid] : 0.0f;
        s[OFF_BCOMB + tid] = (tid < 9) ? bcomb[tid] : 0.0f;
    }
    if (tid < 84) {
        int f = tid / 9, f2 = tid - f * 9;
        s[OFF_WFEAT + tid] = (tid < 81 && f != f2) ? Wfeat[tid] : 0.0f;
    }
    if (tid < TT) s[OFF_INV + tid] = 1.0f / (g_denom[tid] + 1e-5f);

    float* myh = s + OFF_H + row * 68;
    float* myc = s + OFF_C + row * 68;
    float* xcb = s + OFF_XC + row * 13;
    float* ccb = s + OFF_CCB + row * 13;
    if (role == 0) {
        #pragma unroll
        for (int k = 0; k < 64; k++) { myh[k] = 0.0f; myc[k] = 0.0f; }
    }
    __syncthreads();

    const int bb = (b < B) ? b : (B - 1);
    const bool active = (b < B);
    const float* xb = values + (size_t)bb * (TT * FEAT);
    const float* mb = masks + (size_t)bb * (TT * FEAT);
    const float* db = deltas + (size_t)bb * (TT * FEAT);
    float* ob = out + 1 + (size_t)bb * (TT * FEAT);

    const int nf = 5 - role;   // role0: 5 features (even), role1: 4 (odd)
    float loss = 0.0f;
    for (int t = 0; t < TT; t++) {
        float x[9], m[9], d[9];
        #pragma unroll
        for (int f = 0; f < 9; f++) {
            x[f] = xb[t * 9 + f];
            m[f] = mb[t * 9 + f];
            d[f] = db[t * 9 + f];
        }

        // ---- phase A: decay OWN 32 units in place ----
        #pragma unroll
        for (int q8 = 0; q8 < 8; q8++) {
            const int q = qbase + q8;
            const float* w0 = s + OFF_WGH + (4 * q) * 9;
            float a0 = s[OFF_BGH + 4 * q];
            float a1 = s[OFF_BGH + 4 * q + 1];
            float a2 = s[OFF_BGH + 4 * q + 2];
            float a3 = s[OFF_BGH + 4 * q + 3];
            #pragma unroll
            for (int f = 0; f < 9; f++) {
                float dv = d[f];
                a0 = fmaf(dv, w0[f], a0);
                a1 = fmaf(dv, w0[9 + f], a1);
                a2 = fmaf(dv, w0[18 + f], a2);
                a3 = fmaf(dv, w0[27 + f], a3);
            }
            float4 hv = *(const float4*)(myh + 4 * q);
            hv.x *= __expf(-fmaxf(a0, 0.0f));
            hv.y *= __expf(-fmaxf(a1, 0.0f));
            hv.z *= __expf(-fmaxf(a2, 0.0f));
            hv.w *= __expf(-fmaxf(a3, 0.0f));
            *(float4*)(myh + 4 * q) = hv;
        }
        __syncthreads();

        // ---- B1: both roles load the FULL decayed h as pairs ----
        u64 hp[32];
        #pragma unroll
        for (int k = 0; k < 16; k++) {
            float4 v = *(const float4*)(myh + 4 * k);
            hp[2 * k]     = pack2(v.x, v.y);
            hp[2 * k + 1] = pack2(v.z, v.w);
        }
        __syncthreads();   // all h reads done before gates overwrite myh

        // ---- gx for all f (cheap, duplicated) ----
        float gx[9];
        #pragma unroll
        for (int f = 0; f < 9; f++)
            gx[f] = __expf(-fmaxf(fmaf(d[f], s[OFF_WGXD + f], s[OFF_BGX + f]), 0.0f));

        // ---- B2a: hist regression for OWN features (f = 2*fi + role) ----
        float xh_own[5], xc_own[5];
        #pragma unroll
        for (int fi = 0; fi < 5; fi++) {
            if (fi < nf) {
                const int f = 2 * fi + role;
                const float4* wv = (const float4*)(s + OFF_WHIST + f * 64);
                float a0 = s[OFF_BHIST + f], a1 = 0.0f, a2 = 0.0f, a3 = 0.0f;
                #pragma unroll
                for (int q = 0; q < 16; q++) {
                    float4 w4 = wv[q];
                    float2 hA = unpack2(hp[2 * q]);
                    float2 hB = unpack2(hp[2 * q + 1]);
                    a0 = fmaf(hA.x, w4.x, a0);
                    a1 = fmaf(hA.y, w4.y, a1);
                    a2 = fmaf(hB.x, w4.z, a2);
                    a3 = fmaf(hB.y, w4.w, a3);
                }
                float xh = (a0 + a1) + (a2 + a3);
                xh_own[fi] = xh;
                float xc = m[f] * x[f] + (1.0f - m[f]) * xh;
                xc_own[fi] = xc;
                xcb[f] = xc;
            }
        }
        __syncthreads();

        // ---- B2b: feature regression + combine for OWN features ----
        float xcall[9];
        #pragma unroll
        for (int k = 0; k < 9; k++) xcall[k] = xcb[k];
        float lsum = 0.0f;
        #pragma unroll
        for (int fi = 0; fi < 5; fi++) {
            if (fi < nf) {
                const int f = 2 * fi + role;
                const float* wf = s + OFF_WFEAT + f * 9;
                float zh = s[OFF_BFEAT + f];
                #pragma unroll
                for (int k = 0; k < 9; k++) zh = fmaf(xcall[k], wf[k], zh);
                const float* wc = s + OFF_WCOMB + f * 18;
                float al = s[OFF_BCOMB + f];
                #pragma unroll
                for (int k = 0; k < 9; k++) al = fmaf(gx[k], wc[k], al);
                #pragma unroll
                for (int k = 0; k < 9; k++) al = fmaf(m[k], wc[9 + k], al);
                float ch = al * zh + (1.0f - al) * xh_own[fi];
                lsum += m[f] * (fabsf(x[f] - xh_own[fi]) + fabsf(x[f] - zh) + fabsf(x[f] - ch));
                float c_c = m[f] * x[f] + (1.0f - m[f]) * ch;
                if (active) ob[t * 9 + f] = c_c;
                ccb[f] = c_c;
            }
        }
        if (active) loss = fmaf(lsum, s[OFF_INV + t], loss);
        __syncthreads();

        // ---- B2c: assemble inp pairs from exchanged c_c + m ----
        float cc[9];
        #pragma unroll
        for (int k = 0; k < 9; k++) cc[k] = ccb[k];
        u64 inpp[9];
        inpp[0] = pack2(cc[0], cc[1]);
        inpp[1] = pack2(cc[2], cc[3]);
        inpp[2] = pack2(cc[4], cc[5]);
        inpp[3] = pack2(cc[6], cc[7]);
        inpp[4] = pack2(cc[8], m[0]);
        inpp[5] = pack2(m[1], m[2]);
        inpp[6] = pack2(m[3], m[4]);
        inpp[7] = pack2(m[5], m[6]);
        inpp[8] = pack2(m[7], m[8]);

        // ---- gates for OWN 32 units (k-paired f32x2, 4 chains) ----
        #pragma unroll 1
        for (int jj = 0; jj < 32; jj++) {
            const int j = jbase + jj;
            const ulonglong2* wj = (const ulonglong2*)(s + OFF_WG + j * 328);
            const ulonglong2* bj = (const ulonglong2*)(s + OFF_B2 + j * 8);
            ulonglong2 b0 = bj[0], b1 = bj[1];
            u64 aI = b0.x, aF = b0.y, aG = b1.x, aO = b1.y;
            #pragma unroll
            for (int kp = 0; kp < 9; kp++) {
                ulonglong2 w0 = wj[2 * kp];
                ulonglong2 w1 = wj[2 * kp + 1];
                u64 xv = inpp[kp];
                fma2(aI, xv, w0.x);
                fma2(aF, xv, w0.y);
                fma2(aG, xv, w1.x);
                fma2(aO, xv, w1.y);
            }
            #pragma unroll
            for (int kp = 0; kp < 32; kp++) {
                ulonglong2 w0 = wj[18 + 2 * kp];
                ulonglong2 w1 = wj[19 + 2 * kp];
                u64 hv = hp[kp];
                fma2(aI, hv, w0.x);
                fma2(aF, hv, w0.y);
                fma2(aG, hv, w1.x);
                fma2(aO, hv, w1.y);
            }
            float2 vi = unpack2(aI), vf = unpack2(aF);
            float2 vg = unpack2(aG), vo = unpack2(aO);
            float gi = vi.x + vi.y, gf = vf.x + vf.y;
            float gg = vg.x + vg.y, go = vo.x + vo.y;
            float cn = fsigmoid(gf) * myc[j] + fsigmoid(gi) * ftanhx(gg);
            myc[j] = cn;
            myh[j] = fsigmoid(go) * ftanhx(cn);
        }
        // no sync needed: next phase A touches only own units
    }

    // deterministic block reduction of loss (both roles contribute)
    #pragma unroll
    for (int o = 16; o; o >>= 1) loss += __shfl_down_sync(~0u, loss, o);
    __shared__ float red[8];
    if ((tid & 31) == 0) red[tid >> 5] = loss;
    __syncthreads();
    if (tid == 0) {
        float sv = ((red[0] + red[1]) + (red[2] + red[3]))
                 + ((red[4] + red[5]) + (red[6] + red[7]));
        g_partials[blockIdx.x] = sv;
    }
}

__global__ void finalize_kernel(float* __restrict__ out, int nblocks) {
    float sv = 0.0f;
    for (int i = threadIdx.x; i < nblocks; i += 256) sv += g_partials[i];
    __shared__ float red[8];
    #pragma unroll
    for (int o = 16; o; o >>= 1) sv += __shfl_down_sync(~0u, sv, o);
    if ((threadIdx.x & 31) == 0) red[threadIdx.x >> 5] = sv;
    __syncthreads();
    if (threadIdx.x < 8) {
        sv = red[threadIdx.x];
        #pragma unroll
        for (int o = 4; o; o >>= 1) sv += __shfl_down_sync(0xff, sv, o);
        if (threadIdx.x == 0) out[0] = sv * (1.0f / (float)TT);
    }
}

extern "C" void kernel_launch(void* const* d_in, const int* in_sizes, int n_in,
                              void* d_out, int out_size) {
    const float* values = (const float*)d_in[0];
    const float* masks  = (const float*)d_in[1];
    const float* deltas = (const float*)d_in[2];
    const float* Wgh   = (const float*)d_in[3];
    const float* bgh   = (const float*)d_in[4];
    const float* Wgx   = (const float*)d_in[5];
    const float* bgx   = (const float*)d_in[6];
    const float* Whist = (const float*)d_in[7];
    const float* bhist = (const float*)d_in[8];
    const float* Wfeat = (const float*)d_in[9];
    const float* bfeat = (const float*)d_in[10];
    const float* Wcomb = (const float*)d_in[11];
    const float* bcomb = (const float*)d_in[12];
    const float* Wih   = (const float*)d_in[13];
    const float* Whh   = (const float*)d_in[14];
    const float* bih   = (const float*)d_in[15];
    const float* bhh   = (const float*)d_in[16];
    float* out = (float*)d_out;

    int B = in_sizes[0] / (TT * FEAT);
    int nb = (B + BPB - 1) / BPB;

    cudaFuncSetAttribute(rits_main_kernel,
                         cudaFuncAttributeMaxDynamicSharedMemorySize, SMEM_BYTES);

    zero_denom_kernel<<<1, 64>>>();
    denom_kernel<<<(B * TT + 255) / 256, 256>>>(masks, B);
    rits_main_kernel<<<nb, BLK, SMEM_BYTES>>>(
        values, masks, deltas, Wgh, bgh, Wgx, bgx, Whist, bhist,
        Wfeat, bfeat, Wcomb, bcomb, Wih, Whh, bih, bhh, out, B);
    finalize_kernel<<<1, 256>>>(out, nb);
}